// round 1
// baseline (speedup 1.0000x reference)
#include <cuda_runtime.h>
#include <math.h>

// Problem constants
#define NSEQ   1024
#define NBATCH 8
#define NDIM   512
#define NHEADS 8
#define NDH    64
#define NHD    512
#define NFF    2048
#define MROWS  (NBATCH*NSEQ)      // 8192
#define ATT_ELEMS ((size_t)NBATCH*NHEADS*NSEQ*NSEQ)  // 67108864
#define X_ELEMS   ((size_t)MROWS*NDIM)               // 4194304

// ---------------- scratch (device globals; no allocation allowed) ----------
static __device__ float g_x  [MROWS*NDIM];
static __device__ float g_xn [MROWS*NDIM];
static __device__ float g_qkv[MROWS*3*NHD];
static __device__ float g_kr [MROWS*NHD];
static __device__ float g_ac [NBATCH*NHEADS*NSEQ*NSEQ];
static __device__ float g_bd [NBATCH*NHEADS*NSEQ*NSEQ];
static __device__ float g_av [MROWS*NHD];
static __device__ float g_ff [MROWS*NFF];

// ---------------- LayerNorm ------------------------------------------------
// one block (128 threads) per row of 512; float4 per thread
__global__ __launch_bounds__(128) void ln_kernel(
    const float* __restrict__ x, const float* __restrict__ g,
    const float* __restrict__ b, float* __restrict__ y)
{
    const int row = blockIdx.x;
    const int tid = threadIdx.x;
    const float* xr = x + (size_t)row * NDIM;
    float*       yr = y + (size_t)row * NDIM;

    float4 v = ((const float4*)xr)[tid];
    float s  = v.x + v.y + v.z + v.w;
    float sq = v.x*v.x + v.y*v.y + v.z*v.z + v.w*v.w;
#pragma unroll
    for (int o = 16; o > 0; o >>= 1) {
        s  += __shfl_xor_sync(0xffffffffu, s,  o);
        sq += __shfl_xor_sync(0xffffffffu, sq, o);
    }
    __shared__ float red[8];
    const int w = tid >> 5;
    if ((tid & 31) == 0) { red[w] = s; red[4 + w] = sq; }
    __syncthreads();
    const float st  = red[0] + red[1] + red[2] + red[3];
    const float sqt = red[4] + red[5] + red[6] + red[7];
    const float mu  = st * (1.0f / NDIM);
    const float var = sqt * (1.0f / NDIM) - mu * mu;
    const float inv = rsqrtf(var + 1e-5f);

    float4 gg = ((const float4*)g)[tid];
    float4 bb = ((const float4*)b)[tid];
    float4 o;
    o.x = (v.x - mu) * inv * gg.x + bb.x;
    o.y = (v.y - mu) * inv * gg.y + bb.y;
    o.z = (v.z - mu) * inv * gg.z + bb.z;
    o.w = (v.w - mu) * inv * gg.w + bb.w;
    ((float4*)yr)[tid] = o;
}

// ---------------- generic SGEMM: C = A[MxK] * B[KxN] (+bias)(+gelu)(+res) --
__device__ __forceinline__ float gelu_exact(float v) {
    return 0.5f * v * (1.0f + erff(v * 0.70710678118654752f));
}

template<int ACT>  // 0: none, 1: gelu(after bias, before residual)
__global__ __launch_bounds__(256) void sgemm_kernel(
    const float* __restrict__ A, const float* __restrict__ B,
    float* C, const float* __restrict__ bias, const float* res,
    int M, int N, int K)
{
    __shared__ float As[64][17];
    __shared__ float Bs[16][64];
    const int bm = blockIdx.y * 64, bn = blockIdx.x * 64;
    const int tid = threadIdx.x;
    const int tx = tid & 15, ty = tid >> 4;
    const int ar = tid >> 2,  acL = (tid & 3) * 4;   // A loader: 64 rows x 16 cols
    const int br = tid >> 4,  bcL = (tid & 15) * 4;  // B loader: 16 rows x 64 cols
    float acc[4][4] = {};

    for (int k0 = 0; k0 < K; k0 += 16) {
        float4 av = *(const float4*)(A + (size_t)(bm + ar) * K + k0 + acL);
        As[ar][acL + 0] = av.x; As[ar][acL + 1] = av.y;
        As[ar][acL + 2] = av.z; As[ar][acL + 3] = av.w;
        *(float4*)&Bs[br][bcL] = *(const float4*)(B + (size_t)(k0 + br) * N + bn + bcL);
        __syncthreads();
#pragma unroll
        for (int kk = 0; kk < 16; ++kk) {
            float a[4];
#pragma unroll
            for (int ii = 0; ii < 4; ++ii) a[ii] = As[ty * 4 + ii][kk];
            float4 bv = *(const float4*)&Bs[kk][tx * 4];
            const float bb[4] = {bv.x, bv.y, bv.z, bv.w};
#pragma unroll
            for (int ii = 0; ii < 4; ++ii)
#pragma unroll
                for (int jj = 0; jj < 4; ++jj)
                    acc[ii][jj] += a[ii] * bb[jj];
        }
        __syncthreads();
    }
#pragma unroll
    for (int ii = 0; ii < 4; ++ii) {
        const int r = bm + ty * 4 + ii;
#pragma unroll
        for (int jj = 0; jj < 4; ++jj) {
            const int c = bn + tx * 4 + jj;
            float v = acc[ii][jj];
            if (bias) v += bias[c];
            if (ACT == 1) v = gelu_exact(v);
            if (res) v += res[(size_t)r * N + c];
            C[(size_t)r * N + c] = v;
        }
    }
}

// ---------------- AC & BD batched GEMMs (per b,h): Q(+bias_pf) @ K^T, @ KR^T
__global__ __launch_bounds__(256) void acbd_kernel(
    const float* __restrict__ qkv, const float* __restrict__ kr,
    const float* __restrict__ bias_pf,
    float* __restrict__ AC, float* __restrict__ BD)
{
    __shared__ float Qs[64][33], Ks[64][33], Rs[64][33];
    const int bh = blockIdx.z, b = bh >> 3, h = bh & 7;
    const int i0 = blockIdx.y * 64, j0 = blockIdx.x * 64;
    const int tid = threadIdx.x, tx = tid & 15, ty = tid >> 4;

    const size_t qbase = ((size_t)b * NSEQ + i0) * 1536 + h * 64;        // Q
    const size_t kbase = ((size_t)b * NSEQ + j0) * 1536 + 512 + h * 64;  // K
    const size_t rbase = ((size_t)b * NSEQ + j0) * 512 + h * 64;         // KR

    float accA[4][4] = {}, accB[4][4] = {};
    const int lr = tid >> 2, lc = (tid & 3) * 8;  // 64 rows x 32 cols, 8 floats/thread

    for (int d0 = 0; d0 < 64; d0 += 32) {
#pragma unroll
        for (int q = 0; q < 2; ++q) {
            const int c = lc + q * 4;
            float4 qa = *(const float4*)(qkv + qbase + (size_t)lr * 1536 + d0 + c);
            float4 bp = *(const float4*)(bias_pf + h * 64 + d0 + c);
            Qs[lr][c + 0] = qa.x + bp.x; Qs[lr][c + 1] = qa.y + bp.y;
            Qs[lr][c + 2] = qa.z + bp.z; Qs[lr][c + 3] = qa.w + bp.w;
            float4 ka = *(const float4*)(qkv + kbase + (size_t)lr * 1536 + d0 + c);
            Ks[lr][c + 0] = ka.x; Ks[lr][c + 1] = ka.y;
            Ks[lr][c + 2] = ka.z; Ks[lr][c + 3] = ka.w;
            float4 ra = *(const float4*)(kr + rbase + (size_t)lr * 512 + d0 + c);
            Rs[lr][c + 0] = ra.x; Rs[lr][c + 1] = ra.y;
            Rs[lr][c + 2] = ra.z; Rs[lr][c + 3] = ra.w;
        }
        __syncthreads();
#pragma unroll
        for (int dd = 0; dd < 32; ++dd) {
            float a[4], kv[4], rv[4];
#pragma unroll
            for (int ii = 0; ii < 4; ++ii) a[ii] = Qs[ty * 4 + ii][dd];
#pragma unroll
            for (int jj = 0; jj < 4; ++jj) { kv[jj] = Ks[tx * 4 + jj][dd]; rv[jj] = Rs[tx * 4 + jj][dd]; }
#pragma unroll
            for (int ii = 0; ii < 4; ++ii)
#pragma unroll
                for (int jj = 0; jj < 4; ++jj) {
                    accA[ii][jj] += a[ii] * kv[jj];
                    accB[ii][jj] += a[ii] * rv[jj];
                }
        }
        __syncthreads();
    }
    const size_t obase = ((size_t)bh * NSEQ + i0 + ty * 4) * NSEQ + j0 + tx * 4;
#pragma unroll
    for (int ii = 0; ii < 4; ++ii)
#pragma unroll
        for (int jj = 0; jj < 4; ++jj) {
            AC[obase + (size_t)ii * NSEQ + jj] = accA[ii][jj];
            BD[obase + (size_t)ii * NSEQ + jj] = accB[ii][jj];
        }
}

// ---------------- rel_shift + scale + softmax over heads -------------------
// dots[i',j'] = AC[i',j'] + shifted(BDpre)[i',j'] ; softmax over h (8 values)
// shift: g=(i'+1)*N+j'; src_i=g/(N+1); src_j=g%(N+1)-1; zero if src_j<0.
__global__ __launch_bounds__(256) void softmax_shift_kernel(
    const float* AC, const float* __restrict__ BDp, float* attn)
{
    const int j = blockIdx.x * blockDim.x + threadIdx.x;
    const int i = blockIdx.y;
    const int b = blockIdx.z;
    const int g  = (i + 1) * NSEQ + j;
    const int si = g / (NSEQ + 1);
    const int sj = g % (NSEQ + 1) - 1;

    float v[NHEADS];
    float mx = -1e30f;
#pragma unroll
    for (int h = 0; h < NHEADS; ++h) {
        const size_t idx = (((size_t)(b * NHEADS + h)) * NSEQ + i) * NSEQ + j;
        float acv = AC[idx];
        float bdv = 0.0f;
        if (sj >= 0)
            bdv = BDp[(((size_t)(b * NHEADS + h)) * NSEQ + si) * NSEQ + sj];
        const float d = (acv + bdv) * 0.125f;  // SCALE = 64^-0.5
        v[h] = d;
        mx = fmaxf(mx, d);
    }
    float s = 0.0f;
#pragma unroll
    for (int h = 0; h < NHEADS; ++h) { v[h] = __expf(v[h] - mx); s += v[h]; }
    const float inv = 1.0f / s;
#pragma unroll
    for (int h = 0; h < NHEADS; ++h) {
        const size_t idx = (((size_t)(b * NHEADS + h)) * NSEQ + i) * NSEQ + j;
        attn[idx] = v[h] * inv;
    }
}

// ---------------- attn @ V  (per b,h: [N,N]@[N,64]) -------------------------
__global__ __launch_bounds__(256) void av_kernel(
    const float* __restrict__ attn, const float* __restrict__ qkv,
    float* __restrict__ out)
{
    __shared__ float As[64][65];
    __shared__ float Vs[64][64];
    const int bh = blockIdx.y, b = bh >> 3, h = bh & 7;
    const int i0 = blockIdx.x * 64;
    const int tid = threadIdx.x, tx = tid & 15, ty = tid >> 4;

    const float* abase = attn + ((size_t)bh * NSEQ + i0) * NSEQ;
    const size_t vcol = 1024 + (size_t)h * 64;
    float acc[4][4] = {};
    const int lr = tid >> 2, lc = (tid & 3) * 16;  // 64 rows, 16 floats per thread

    for (int j0 = 0; j0 < NSEQ; j0 += 64) {
#pragma unroll
        for (int q = 0; q < 4; ++q) {
            const int c = lc + q * 4;
            float4 t = *(const float4*)(abase + (size_t)lr * NSEQ + j0 + c);
            As[lr][c + 0] = t.x; As[lr][c + 1] = t.y; As[lr][c + 2] = t.z; As[lr][c + 3] = t.w;
            float4 vt = *(const float4*)(qkv + ((size_t)b * NSEQ + j0 + lr) * 1536 + vcol + c);
            *(float4*)&Vs[lr][c] = vt;
        }
        __syncthreads();
#pragma unroll
        for (int kk = 0; kk < 64; ++kk) {
            float a[4];
#pragma unroll
            for (int ii = 0; ii < 4; ++ii) a[ii] = As[ty * 4 + ii][kk];
            float4 bv = *(const float4*)&Vs[kk][tx * 4];
            const float bb[4] = {bv.x, bv.y, bv.z, bv.w};
#pragma unroll
            for (int ii = 0; ii < 4; ++ii)
#pragma unroll
                for (int jj = 0; jj < 4; ++jj)
                    acc[ii][jj] += a[ii] * bb[jj];
        }
        __syncthreads();
    }
#pragma unroll
    for (int ii = 0; ii < 4; ++ii)
#pragma unroll
        for (int jj = 0; jj < 4; ++jj)
            out[((size_t)b * NSEQ + i0 + ty * 4 + ii) * NHD + h * 64 + tx * 4 + jj] = acc[ii][jj];
}

// ---------------- host orchestration ---------------------------------------
extern "C" void kernel_launch(void* const* d_in, const int* in_sizes, int n_in,
                              void* d_out, int out_size)
{
    (void)in_sizes; (void)n_in;
    const float* x_in    = (const float*)d_in[0];
    const float* r_t     = (const float*)d_in[1];
    // d_in[2] r_p: unused (reference discards BD_p)
    const float* bias_pf = (const float*)d_in[3];
    const float* ln1_g   = (const float*)d_in[4];
    const float* ln1_b   = (const float*)d_in[5];
    const float* Wqkv    = (const float*)d_in[6];
    const float* Wkr_t   = (const float*)d_in[7];
    // d_in[8] Wkr_p: unused
    const float* Wout    = (const float*)d_in[9];
    const float* bout    = (const float*)d_in[10];
    const float* ln2_g   = (const float*)d_in[11];
    const float* ln2_b   = (const float*)d_in[12];
    const float* W1      = (const float*)d_in[13];
    const float* b1      = (const float*)d_in[14];
    const float* W2      = (const float*)d_in[15];
    const float* b2      = (const float*)d_in[16];
    float* outp = (float*)d_out;

    float *gx, *gxn, *gqkv, *gkr, *gac, *gbd, *gav, *gff;
    cudaGetSymbolAddress((void**)&gx,   g_x);
    cudaGetSymbolAddress((void**)&gxn,  g_xn);
    cudaGetSymbolAddress((void**)&gqkv, g_qkv);
    cudaGetSymbolAddress((void**)&gkr,  g_kr);
    cudaGetSymbolAddress((void**)&gac,  g_ac);
    cudaGetSymbolAddress((void**)&gbd,  g_bd);
    cudaGetSymbolAddress((void**)&gav,  g_av);
    cudaGetSymbolAddress((void**)&gff,  g_ff);

    // attention output region: (x first, attention second in flattened tuple)
    float* attn_out = outp + ((size_t)out_size - ATT_ELEMS);

    cudaMemcpyAsync(gx, x_in, X_ELEMS * sizeof(float), cudaMemcpyDeviceToDevice, 0);

    for (int l = 0; l < 4; ++l) {
        // PreNorm + QKV + relative key projection
        ln_kernel<<<MROWS, 128>>>(gx, ln1_g + l * NDIM, ln1_b + l * NDIM, gxn);
        sgemm_kernel<0><<<dim3(3 * NHD / 64, MROWS / 64), 256>>>(
            gxn, Wqkv + (size_t)l * NDIM * 3 * NHD, gqkv, nullptr, nullptr,
            MROWS, 3 * NHD, NDIM);
        sgemm_kernel<0><<<dim3(NHD / 64, MROWS / 64), 256>>>(
            r_t, Wkr_t + (size_t)l * NDIM * NHD, gkr, nullptr, nullptr,
            MROWS, NHD, NDIM);

        // batched AC = (q+bias_pf)K^T  and BDpre = (q+bias_pf)KR^T
        acbd_kernel<<<dim3(NSEQ / 64, NSEQ / 64, NBATCH * NHEADS), 256>>>(
            gqkv, gkr, bias_pf, gac, gbd);

        // rel_shift + scale + softmax over heads (in place; last layer -> d_out)
        float* attn = (l == 3) ? attn_out : gac;
        softmax_shift_kernel<<<dim3(NSEQ / 256, NSEQ, NBATCH), 256>>>(gac, gbd, attn);

        // out = attn @ V  -> [8192, 512]
        av_kernel<<<dim3(NSEQ / 64, NBATCH * NHEADS), 256>>>(attn, gqkv, gav);

        // x = out @ Wout + bout + x
        sgemm_kernel<0><<<dim3(NDIM / 64, MROWS / 64), 256>>>(
            gav, Wout + (size_t)l * NHD * NDIM, gx, bout + l * NDIM, gx,
            MROWS, NDIM, NHD);

        // FFN: x = gelu(ln2(x)@W1+b1)@W2 + b2 + x
        ln_kernel<<<MROWS, 128>>>(gx, ln2_g + l * NDIM, ln2_b + l * NDIM, gxn);
        sgemm_kernel<1><<<dim3(NFF / 64, MROWS / 64), 256>>>(
            gxn, W1 + (size_t)l * NDIM * NFF, gff, b1 + l * NFF, nullptr,
            MROWS, NFF, NDIM);
        float* xdst = (l == 3) ? outp : gx;
        sgemm_kernel<0><<<dim3(NDIM / 64, MROWS / 64), 256>>>(
            gff, W2 + (size_t)l * NFF * NDIM, xdst, b2 + l * NDIM, gx,
            MROWS, NDIM, NFF);
    }
}

// round 3
// speedup vs baseline: 1.6065x; 1.6065x over previous
#include <cuda_runtime.h>
#include <cuda_bf16.h>
#include <math.h>
#include <stdint.h>

// Problem constants
#define NSEQ   1024
#define NBATCH 8
#define NDIM   512
#define NHEADS 8
#define NDH    64
#define NHD    512
#define NFF    2048
#define MROWS  (NBATCH*NSEQ)      // 8192
#define ATT_ELEMS ((size_t)NBATCH*NHEADS*NSEQ*NSEQ)
#define X_ELEMS   ((size_t)MROWS*NDIM)

// transposed weight scratch offsets (floats)
#define WQKVT 0
#define WKRT  786432
#define WOUTT 1048576
#define W1T   1310720
#define W2T   2359296
#define WT_TOTAL 3407872

// ---------------- scratch (device globals) ----------------------------------
static __device__ float g_x  [MROWS*NDIM];
static __device__ float g_xn [MROWS*NDIM];
static __device__ float g_qkv[MROWS*3*NHD];
static __device__ float g_kr [MROWS*NHD];
static __device__ float g_ac [NBATCH*NHEADS*NSEQ*NSEQ];
static __device__ float g_bd [NBATCH*NHEADS*NSEQ*NSEQ];
static __device__ float g_av [MROWS*NHD];
static __device__ float g_ff [MROWS*NFF];
static __device__ float g_wt [WT_TOTAL];

// ---------------- helpers ----------------------------------------------------
__device__ __forceinline__ uint32_t smem_u32(const void* p) {
    uint32_t a;
    asm("{ .reg .u64 t; cvta.to.shared.u64 t, %1; cvt.u32.u64 %0, t; }"
        : "=r"(a) : "l"(p));
    return a;
}

__device__ __forceinline__ void mma_bf16(float* d, const uint32_t* a, const uint32_t* b) {
    asm volatile(
        "mma.sync.aligned.m16n8k16.row.col.f32.bf16.bf16.f32 "
        "{%0,%1,%2,%3}, {%4,%5,%6,%7}, {%8,%9}, {%0,%1,%2,%3};"
        : "+f"(d[0]), "+f"(d[1]), "+f"(d[2]), "+f"(d[3])
        : "r"(a[0]), "r"(a[1]), "r"(a[2]), "r"(a[3]), "r"(b[0]), "r"(b[1]));
}

__device__ __forceinline__ void ldm_x4(uint32_t* r, uint32_t addr) {
    asm volatile("ldmatrix.sync.aligned.m8n8.x4.shared.b16 {%0,%1,%2,%3}, [%4];"
        : "=r"(r[0]), "=r"(r[1]), "=r"(r[2]), "=r"(r[3]) : "r"(addr));
}
__device__ __forceinline__ void ldm_x2(uint32_t* r, uint32_t addr) {
    asm volatile("ldmatrix.sync.aligned.m8n8.x2.shared.b16 {%0,%1}, [%2];"
        : "=r"(r[0]), "=r"(r[1]) : "r"(addr));
}

__device__ __forceinline__ float gelu_exact(float v) {
    return 0.5f * v * (1.0f + erff(v * 0.70710678118654752f));
}

__device__ __forceinline__ uint32_t pack_hi(float x, float y,
                                            float& lx, float& ly) {
    __nv_bfloat16 hx = __float2bfloat16_rn(x);
    __nv_bfloat16 hy = __float2bfloat16_rn(y);
    lx = x - __bfloat162float(hx);
    ly = y - __bfloat162float(hy);
    __nv_bfloat162 h; h.x = hx; h.y = hy;
    return *(uint32_t*)&h;
}
__device__ __forceinline__ uint32_t pack_bf2(float x, float y) {
    __nv_bfloat162 h; h.x = __float2bfloat16_rn(x); h.y = __float2bfloat16_rn(y);
    return *(uint32_t*)&h;
}

// ================= weight transpose: W[K][N] -> Wt[N][K] =====================
__global__ __launch_bounds__(256) void transpose_kernel(
    const float* __restrict__ W, float* __restrict__ Wt, int K, int N)
{
    __shared__ float t[32][33];
    const int k0 = blockIdx.y * 32, n0 = blockIdx.x * 32;
    const int x = threadIdx.x, y = threadIdx.y;  // 32 x 8
#pragma unroll
    for (int i = 0; i < 32; i += 8)
        t[y + i][x] = W[(size_t)(k0 + y + i) * N + n0 + x];
    __syncthreads();
#pragma unroll
    for (int i = 0; i < 32; i += 8)
        Wt[(size_t)(n0 + y + i) * K + k0 + x] = t[x][y + i];
}

// ================ bf16x3 mma GEMM: C = A[M,K] @ Bt[N,K]^T ====================
// 128x128 CTA tile, k-step 32, 8 warps (2x4), warp tile 64x32.
// smem pitch 40 bf16 (80B) -> conflict-free ldmatrix.
#define LDS 40

__global__ __launch_bounds__(256, 2) void mma_gemm_kernel(
    const float* __restrict__ A, const float* __restrict__ Bt,
    float* __restrict__ C, const float* __restrict__ bias,
    const float* __restrict__ res, int M, int N, int K, int act)
{
    __shared__ __nv_bfloat16 sAh[128 * LDS];
    __shared__ __nv_bfloat16 sAl[128 * LDS];
    __shared__ __nv_bfloat16 sBh[128 * LDS];
    __shared__ __nv_bfloat16 sBl[128 * LDS];

    const int tid = threadIdx.x, wid = tid >> 5, lane = tid & 31;
    const int wm = wid >> 2, wn = wid & 3;         // 2 x 4 warp grid
    const int bm = blockIdx.y * 128, bn = blockIdx.x * 128;

    const uint32_t aAh = smem_u32(sAh), aAl = smem_u32(sAl);
    const uint32_t aBh = smem_u32(sBh), aBl = smem_u32(sBl);

    // per-lane ldmatrix byte offsets
    const int l15 = lane & 15;
    const uint32_t aoff = (uint32_t)(((wm * 64 + l15) * LDS + ((lane >> 4) << 3)) * 2);
    const uint32_t boff = (uint32_t)(((wn * 32 + (l15 & 7)) * LDS + (((l15 >> 3) & 1) << 3)) * 2);

    float acc[4][4][4];
#pragma unroll
    for (int i = 0; i < 4; ++i)
#pragma unroll
        for (int j = 0; j < 4; ++j)
#pragma unroll
            for (int q = 0; q < 4; ++q) acc[i][j][q] = 0.0f;

    const int NKT = K >> 5;
    for (int kt = 0; kt < NKT; ++kt) {
        const int k0 = kt * 32;
        // ---- load fp32, split into bf16 hi/lo, store to smem ----
#pragma unroll
        for (int i = 0; i < 4; ++i) {
            const int idx = tid + i * 256;          // 0..1023
            const int row = idx >> 3, cg = (idx & 7) * 4;
            const uint32_t so = (uint32_t)((row * LDS + cg) * 2);

            float4 v = *(const float4*)(A + (size_t)(bm + row) * K + k0 + cg);
            float lx, ly, lz, lw;
            uint32_t h0 = pack_hi(v.x, v.y, lx, ly);
            uint32_t h1 = pack_hi(v.z, v.w, lz, lw);
            *(uint2*)((char*)sAh + so) = make_uint2(h0, h1);
            *(uint2*)((char*)sAl + so) = make_uint2(pack_bf2(lx, ly), pack_bf2(lz, lw));

            float4 b = *(const float4*)(Bt + (size_t)(bn + row) * K + k0 + cg);
            uint32_t g0 = pack_hi(b.x, b.y, lx, ly);
            uint32_t g1 = pack_hi(b.z, b.w, lz, lw);
            *(uint2*)((char*)sBh + so) = make_uint2(g0, g1);
            *(uint2*)((char*)sBl + so) = make_uint2(pack_bf2(lx, ly), pack_bf2(lz, lw));
        }
        __syncthreads();

        // ---- mma over kk in {0,16}: HH, HL, then LH ----
#pragma unroll
        for (int kk = 0; kk < 32; kk += 16) {
            uint32_t bh[4][2], bl[4][2], a[4][4];
#pragma unroll
            for (int nt = 0; nt < 4; ++nt) {
                const uint32_t bo = boff + (uint32_t)((nt * 8 * LDS + kk) * 2);
                ldm_x2(bh[nt], aBh + bo);
                ldm_x2(bl[nt], aBl + bo);
            }
#pragma unroll
            for (int mt = 0; mt < 4; ++mt)
                ldm_x4(a[mt], aAh + aoff + (uint32_t)((mt * 16 * LDS + kk) * 2));
#pragma unroll
            for (int mt = 0; mt < 4; ++mt)
#pragma unroll
                for (int nt = 0; nt < 4; ++nt) {
                    mma_bf16(acc[mt][nt], a[mt], bh[nt]);   // ah*bh
                    mma_bf16(acc[mt][nt], a[mt], bl[nt]);   // ah*bl
                }
#pragma unroll
            for (int mt = 0; mt < 4; ++mt)
                ldm_x4(a[mt], aAl + aoff + (uint32_t)((mt * 16 * LDS + kk) * 2));
#pragma unroll
            for (int mt = 0; mt < 4; ++mt)
#pragma unroll
                for (int nt = 0; nt < 4; ++nt)
                    mma_bf16(acc[mt][nt], a[mt], bh[nt]);   // al*bh
        }
        __syncthreads();
    }

    // ---- epilogue ----
    const int g = lane >> 2, t2 = (lane & 3) * 2;
#pragma unroll
    for (int mt = 0; mt < 4; ++mt) {
#pragma unroll
        for (int nt = 0; nt < 4; ++nt) {
            const int r0 = bm + wm * 64 + mt * 16 + g;
            const int r1 = r0 + 8;
            const int c  = bn + wn * 32 + nt * 8 + t2;
            float v0 = acc[mt][nt][0], v1 = acc[mt][nt][1];
            float v2 = acc[mt][nt][2], v3 = acc[mt][nt][3];
            if (bias) {
                const float b0 = bias[c], b1 = bias[c + 1];
                v0 += b0; v1 += b1; v2 += b0; v3 += b1;
            }
            if (act) {
                v0 = gelu_exact(v0); v1 = gelu_exact(v1);
                v2 = gelu_exact(v2); v3 = gelu_exact(v3);
            }
            if (res) {
                const float2 q0 = *(const float2*)(res + (size_t)r0 * N + c);
                const float2 q1 = *(const float2*)(res + (size_t)r1 * N + c);
                v0 += q0.x; v1 += q0.y; v2 += q1.x; v3 += q1.y;
            }
            *(float2*)(C + (size_t)r0 * N + c) = make_float2(v0, v1);
            *(float2*)(C + (size_t)r1 * N + c) = make_float2(v2, v3);
        }
    }
}

// ---------------- LayerNorm ------------------------------------------------
__global__ __launch_bounds__(128) void ln_kernel(
    const float* __restrict__ x, const float* __restrict__ g,
    const float* __restrict__ b, float* __restrict__ y)
{
    const int row = blockIdx.x;
    const int tid = threadIdx.x;
    const float* xr = x + (size_t)row * NDIM;
    float*       yr = y + (size_t)row * NDIM;

    float4 v = ((const float4*)xr)[tid];
    float s  = v.x + v.y + v.z + v.w;
    float sq = v.x*v.x + v.y*v.y + v.z*v.z + v.w*v.w;
#pragma unroll
    for (int o = 16; o > 0; o >>= 1) {
        s  += __shfl_xor_sync(0xffffffffu, s,  o);
        sq += __shfl_xor_sync(0xffffffffu, sq, o);
    }
    __shared__ float red[8];
    const int w = tid >> 5;
    if ((tid & 31) == 0) { red[w] = s; red[4 + w] = sq; }
    __syncthreads();
    const float st  = red[0] + red[1] + red[2] + red[3];
    const float sqt = red[4] + red[5] + red[6] + red[7];
    const float mu  = st * (1.0f / NDIM);
    const float var = sqt * (1.0f / NDIM) - mu * mu;
    const float inv = rsqrtf(var + 1e-5f);

    float4 gg = ((const float4*)g)[tid];
    float4 bb = ((const float4*)b)[tid];
    float4 o;
    o.x = (v.x - mu) * inv * gg.x + bb.x;
    o.y = (v.y - mu) * inv * gg.y + bb.y;
    o.z = (v.z - mu) * inv * gg.z + bb.z;
    o.w = (v.w - mu) * inv * gg.w + bb.w;
    ((float4*)yr)[tid] = o;
}

// ---------------- AC & BD batched GEMMs (per b,h) ---------------------------
__global__ __launch_bounds__(256) void acbd_kernel(
    const float* __restrict__ qkv, const float* __restrict__ kr,
    const float* __restrict__ bias_pf,
    float* __restrict__ AC, float* __restrict__ BD)
{
    __shared__ float Qs[64][33], Ks[64][33], Rs[64][33];
    const int bh = blockIdx.z, b = bh >> 3, h = bh & 7;
    const int i0 = blockIdx.y * 64, j0 = blockIdx.x * 64;
    const int tid = threadIdx.x, tx = tid & 15, ty = tid >> 4;

    const size_t qbase = ((size_t)b * NSEQ + i0) * 1536 + h * 64;
    const size_t kbase = ((size_t)b * NSEQ + j0) * 1536 + 512 + h * 64;
    const size_t rbase = ((size_t)b * NSEQ + j0) * 512 + h * 64;

    float accA[4][4] = {}, accB[4][4] = {};
    const int lr = tid >> 2, lc = (tid & 3) * 8;

    for (int d0 = 0; d0 < 64; d0 += 32) {
#pragma unroll
        for (int q = 0; q < 2; ++q) {
            const int c = lc + q * 4;
            float4 qa = *(const float4*)(qkv + qbase + (size_t)lr * 1536 + d0 + c);
            float4 bp = *(const float4*)(bias_pf + h * 64 + d0 + c);
            Qs[lr][c + 0] = qa.x + bp.x; Qs[lr][c + 1] = qa.y + bp.y;
            Qs[lr][c + 2] = qa.z + bp.z; Qs[lr][c + 3] = qa.w + bp.w;
            float4 ka = *(const float4*)(qkv + kbase + (size_t)lr * 1536 + d0 + c);
            Ks[lr][c + 0] = ka.x; Ks[lr][c + 1] = ka.y;
            Ks[lr][c + 2] = ka.z; Ks[lr][c + 3] = ka.w;
            float4 ra = *(const float4*)(kr + rbase + (size_t)lr * 512 + d0 + c);
            Rs[lr][c + 0] = ra.x; Rs[lr][c + 1] = ra.y;
            Rs[lr][c + 2] = ra.z; Rs[lr][c + 3] = ra.w;
        }
        __syncthreads();
#pragma unroll
        for (int dd = 0; dd < 32; ++dd) {
            float a[4], kv[4], rv[4];
#pragma unroll
            for (int ii = 0; ii < 4; ++ii) a[ii] = Qs[ty * 4 + ii][dd];
#pragma unroll
            for (int jj = 0; jj < 4; ++jj) { kv[jj] = Ks[tx * 4 + jj][dd]; rv[jj] = Rs[tx * 4 + jj][dd]; }
#pragma unroll
            for (int ii = 0; ii < 4; ++ii)
#pragma unroll
                for (int jj = 0; jj < 4; ++jj) {
                    accA[ii][jj] += a[ii] * kv[jj];
                    accB[ii][jj] += a[ii] * rv[jj];
                }
        }
        __syncthreads();
    }
    const size_t obase = ((size_t)bh * NSEQ + i0 + ty * 4) * NSEQ + j0 + tx * 4;
#pragma unroll
    for (int ii = 0; ii < 4; ++ii)
#pragma unroll
        for (int jj = 0; jj < 4; ++jj) {
            AC[obase + (size_t)ii * NSEQ + jj] = accA[ii][jj];
            BD[obase + (size_t)ii * NSEQ + jj] = accB[ii][jj];
        }
}

// ---------------- rel_shift + scale + softmax over heads -------------------
__global__ __launch_bounds__(256) void softmax_shift_kernel(
    const float* AC, const float* __restrict__ BDp, float* attn)
{
    const int j = blockIdx.x * blockDim.x + threadIdx.x;
    const int i = blockIdx.y;
    const int b = blockIdx.z;
    const int g  = (i + 1) * NSEQ + j;
    const int si = g / (NSEQ + 1);
    const int sj = g % (NSEQ + 1) - 1;

    float v[NHEADS];
    float mx = -1e30f;
#pragma unroll
    for (int h = 0; h < NHEADS; ++h) {
        const size_t idx = (((size_t)(b * NHEADS + h)) * NSEQ + i) * NSEQ + j;
        float acv = AC[idx];
        float bdv = 0.0f;
        if (sj >= 0)
            bdv = BDp[(((size_t)(b * NHEADS + h)) * NSEQ + si) * NSEQ + sj];
        const float d = (acv + bdv) * 0.125f;
        v[h] = d;
        mx = fmaxf(mx, d);
    }
    float s = 0.0f;
#pragma unroll
    for (int h = 0; h < NHEADS; ++h) { v[h] = __expf(v[h] - mx); s += v[h]; }
    const float inv = 1.0f / s;
#pragma unroll
    for (int h = 0; h < NHEADS; ++h) {
        const size_t idx = (((size_t)(b * NHEADS + h)) * NSEQ + i) * NSEQ + j;
        attn[idx] = v[h] * inv;
    }
}

// ---------------- attn @ V  (per b,h: [N,N]@[N,64]) -------------------------
__global__ __launch_bounds__(256) void av_kernel(
    const float* __restrict__ attn, const float* __restrict__ qkv,
    float* __restrict__ out)
{
    __shared__ float As[64][65];
    __shared__ float Vs[64][64];
    const int bh = blockIdx.y, b = bh >> 3, h = bh & 7;
    const int i0 = blockIdx.x * 64;
    const int tid = threadIdx.x, tx = tid & 15, ty = tid >> 4;

    const float* abase = attn + ((size_t)bh * NSEQ + i0) * NSEQ;
    const size_t vcol = 1024 + (size_t)h * 64;
    float acc[4][4] = {};
    const int lr = tid >> 2, lc = (tid & 3) * 16;

    for (int j0 = 0; j0 < NSEQ; j0 += 64) {
#pragma unroll
        for (int q = 0; q < 4; ++q) {
            const int c = lc + q * 4;
            float4 t = *(const float4*)(abase + (size_t)lr * NSEQ + j0 + c);
            As[lr][c + 0] = t.x; As[lr][c + 1] = t.y; As[lr][c + 2] = t.z; As[lr][c + 3] = t.w;
            float4 vt = *(const float4*)(qkv + ((size_t)b * NSEQ + j0 + lr) * 1536 + vcol + c);
            *(float4*)&Vs[lr][c] = vt;
        }
        __syncthreads();
#pragma unroll
        for (int kk = 0; kk < 64; ++kk) {
            float a[4];
#pragma unroll
            for (int ii = 0; ii < 4; ++ii) a[ii] = As[ty * 4 + ii][kk];
            float4 bv = *(const float4*)&Vs[kk][tx * 4];
            const float bb[4] = {bv.x, bv.y, bv.z, bv.w};
#pragma unroll
            for (int ii = 0; ii < 4; ++ii)
#pragma unroll
                for (int jj = 0; jj < 4; ++jj)
                    acc[ii][jj] += a[ii] * bb[jj];
        }
        __syncthreads();
    }
#pragma unroll
    for (int ii = 0; ii < 4; ++ii)
#pragma unroll
        for (int jj = 0; jj < 4; ++jj)
            out[((size_t)b * NSEQ + i0 + ty * 4 + ii) * NHD + h * 64 + tx * 4 + jj] = acc[ii][jj];
}

// ---------------- host orchestration ---------------------------------------
extern "C" void kernel_launch(void* const* d_in, const int* in_sizes, int n_in,
                              void* d_out, int out_size)
{
    (void)in_sizes; (void)n_in;
    const float* x_in    = (const float*)d_in[0];
    const float* r_t     = (const float*)d_in[1];
    const float* bias_pf = (const float*)d_in[3];
    const float* ln1_g   = (const float*)d_in[4];
    const float* ln1_b   = (const float*)d_in[5];
    const float* Wqkv    = (const float*)d_in[6];
    const float* Wkr_t   = (const float*)d_in[7];
    const float* Wout    = (const float*)d_in[9];
    const float* bout    = (const float*)d_in[10];
    const float* ln2_g   = (const float*)d_in[11];
    const float* ln2_b   = (const float*)d_in[12];
    const float* W1      = (const float*)d_in[13];
    const float* b1      = (const float*)d_in[14];
    const float* W2      = (const float*)d_in[15];
    const float* b2      = (const float*)d_in[16];
    float* outp = (float*)d_out;

    float *gx, *gxn, *gqkv, *gkr, *gac, *gbd, *gav, *gff, *gwt;
    cudaGetSymbolAddress((void**)&gx,   g_x);
    cudaGetSymbolAddress((void**)&gxn,  g_xn);
    cudaGetSymbolAddress((void**)&gqkv, g_qkv);
    cudaGetSymbolAddress((void**)&gkr,  g_kr);
    cudaGetSymbolAddress((void**)&gac,  g_ac);
    cudaGetSymbolAddress((void**)&gbd,  g_bd);
    cudaGetSymbolAddress((void**)&gav,  g_av);
    cudaGetSymbolAddress((void**)&gff,  g_ff);
    cudaGetSymbolAddress((void**)&gwt,  g_wt);

    float* attn_out = outp + ((size_t)out_size - ATT_ELEMS);

    cudaMemcpyAsync(gx, x_in, X_ELEMS * sizeof(float), cudaMemcpyDeviceToDevice, 0);

    const dim3 tb(32, 8);
    for (int l = 0; l < 4; ++l) {
        // transpose this layer's weights into [N][K]
        transpose_kernel<<<dim3(1536/32, 512/32), tb>>>(Wqkv  + (size_t)l*512*1536, gwt + WQKVT, 512, 1536);
        transpose_kernel<<<dim3(512/32,  512/32), tb>>>(Wkr_t + (size_t)l*512*512,  gwt + WKRT,  512, 512);
        transpose_kernel<<<dim3(512/32,  512/32), tb>>>(Wout  + (size_t)l*512*512,  gwt + WOUTT, 512, 512);
        transpose_kernel<<<dim3(2048/32, 512/32), tb>>>(W1    + (size_t)l*512*2048, gwt + W1T,   512, 2048);
        transpose_kernel<<<dim3(512/32, 2048/32), tb>>>(W2    + (size_t)l*2048*512, gwt + W2T,  2048, 512);

        // PreNorm + QKV + relative key projection (bf16x3 mma)
        ln_kernel<<<MROWS, 128>>>(gx, ln1_g + l * NDIM, ln1_b + l * NDIM, gxn);
        mma_gemm_kernel<<<dim3(12, 64), 256>>>(
            gxn, gwt + WQKVT, gqkv, nullptr, nullptr, MROWS, 1536, 512, 0);
        mma_gemm_kernel<<<dim3(4, 64), 256>>>(
            r_t, gwt + WKRT, gkr, nullptr, nullptr, MROWS, 512, 512, 0);

        // batched AC / BD
        acbd_kernel<<<dim3(NSEQ / 64, NSEQ / 64, NBATCH * NHEADS), 256>>>(
            gqkv, gkr, bias_pf, gac, gbd);

        // rel_shift + scale + softmax over heads
        float* attn = (l == 3) ? attn_out : gac;
        softmax_shift_kernel<<<dim3(NSEQ / 256, NSEQ, NBATCH), 256>>>(gac, gbd, attn);

        // out = attn @ V
        av_kernel<<<dim3(NSEQ / 64, NBATCH * NHEADS), 256>>>(attn, gqkv, gav);

        // x = out @ Wout + bout + x
        mma_gemm_kernel<<<dim3(4, 64), 256>>>(
            gav, gwt + WOUTT, gx, bout + l * NDIM, gx, MROWS, 512, 512, 0);

        // FFN
        ln_kernel<<<MROWS, 128>>>(gx, ln2_g + l * NDIM, ln2_b + l * NDIM, gxn);
        mma_gemm_kernel<<<dim3(16, 64), 256>>>(
            gxn, gwt + W1T, gff, b1 + l * NFF, nullptr, MROWS, 2048, 512, 1);
        float* xdst = (l == 3) ? outp : gx;
        mma_gemm_kernel<<<dim3(4, 64), 256>>>(
            gff, gwt + W2T, xdst, b2 + l * NDIM, gx, MROWS, 512, 2048, 0);
    }
}

// round 4
// speedup vs baseline: 2.4174x; 1.5047x over previous
#include <cuda_runtime.h>
#include <cuda_bf16.h>
#include <math.h>
#include <stdint.h>

// Problem constants
#define NSEQ   1024
#define NBATCH 8
#define NDIM   512
#define NHEADS 8
#define NDH    64
#define NHD    512
#define NFF    2048
#define MROWS  (NBATCH*NSEQ)      // 8192
#define ATT_ELEMS ((size_t)NBATCH*NHEADS*NSEQ*NSEQ)
#define X_ELEMS   ((size_t)MROWS*NDIM)

// transposed weight scratch offsets (floats)
#define WQKVT 0
#define WKRT  786432
#define WOUTT 1048576
#define W1T   1310720
#define W2T   2359296
#define WT_TOTAL 3407872

// ---------------- scratch (device globals) ----------------------------------
static __device__ float g_x  [MROWS*NDIM];
static __device__ float g_xn [MROWS*NDIM];
static __device__ float g_qkv[MROWS*3*NHD];
static __device__ float g_kr [MROWS*NHD];
static __device__ float g_ac [NBATCH*NHEADS*NSEQ*NSEQ];
static __device__ float g_bd [NBATCH*NHEADS*NSEQ*NSEQ];
static __device__ float g_av [MROWS*NHD];
static __device__ float g_ff [MROWS*NFF];
static __device__ float g_wt [WT_TOTAL];
static __device__ float g_vt [NBATCH*NHEADS*NDH*NSEQ];  // V transposed per (b,h): [d][j]

// ---------------- helpers ----------------------------------------------------
__device__ __forceinline__ uint32_t smem_u32(const void* p) {
    uint32_t a;
    asm("{ .reg .u64 t; cvta.to.shared.u64 t, %1; cvt.u32.u64 %0, t; }"
        : "=r"(a) : "l"(p));
    return a;
}

__device__ __forceinline__ void mma_bf16(float* d, const uint32_t* a, const uint32_t* b) {
    asm volatile(
        "mma.sync.aligned.m16n8k16.row.col.f32.bf16.bf16.f32 "
        "{%0,%1,%2,%3}, {%4,%5,%6,%7}, {%8,%9}, {%0,%1,%2,%3};"
        : "+f"(d[0]), "+f"(d[1]), "+f"(d[2]), "+f"(d[3])
        : "r"(a[0]), "r"(a[1]), "r"(a[2]), "r"(a[3]), "r"(b[0]), "r"(b[1]));
}

__device__ __forceinline__ void ldm_x4(uint32_t* r, uint32_t addr) {
    asm volatile("ldmatrix.sync.aligned.m8n8.x4.shared.b16 {%0,%1,%2,%3}, [%4];"
        : "=r"(r[0]), "=r"(r[1]), "=r"(r[2]), "=r"(r[3]) : "r"(addr));
}
__device__ __forceinline__ void ldm_x2(uint32_t* r, uint32_t addr) {
    asm volatile("ldmatrix.sync.aligned.m8n8.x2.shared.b16 {%0,%1}, [%2];"
        : "=r"(r[0]), "=r"(r[1]) : "r"(addr));
}

__device__ __forceinline__ float gelu_exact(float v) {
    return 0.5f * v * (1.0f + erff(v * 0.70710678118654752f));
}

__device__ __forceinline__ uint32_t pack_hi(float x, float y,
                                            float& lx, float& ly) {
    __nv_bfloat16 hx = __float2bfloat16_rn(x);
    __nv_bfloat16 hy = __float2bfloat16_rn(y);
    lx = x - __bfloat162float(hx);
    ly = y - __bfloat162float(hy);
    __nv_bfloat162 h; h.x = hx; h.y = hy;
    return *(uint32_t*)&h;
}
__device__ __forceinline__ uint32_t pack_bf2(float x, float y) {
    __nv_bfloat162 h; h.x = __float2bfloat16_rn(x); h.y = __float2bfloat16_rn(y);
    return *(uint32_t*)&h;
}

// split a float4 into hi/lo packed bf16 pairs
__device__ __forceinline__ void split4(float4 v, uint2& hi, uint2& lo) {
    float lx, ly, lz, lw;
    uint32_t h0 = pack_hi(v.x, v.y, lx, ly);
    uint32_t h1 = pack_hi(v.z, v.w, lz, lw);
    hi = make_uint2(h0, h1);
    lo = make_uint2(pack_bf2(lx, ly), pack_bf2(lz, lw));
}

// ================= weight transpose: W[K][N] -> Wt[N][K] =====================
__global__ __launch_bounds__(256) void transpose_kernel(
    const float* __restrict__ W, float* __restrict__ Wt, int K, int N)
{
    __shared__ float t[32][33];
    const int k0 = blockIdx.y * 32, n0 = blockIdx.x * 32;
    const int x = threadIdx.x, y = threadIdx.y;  // 32 x 8
#pragma unroll
    for (int i = 0; i < 32; i += 8)
        t[y + i][x] = W[(size_t)(k0 + y + i) * N + n0 + x];
    __syncthreads();
#pragma unroll
    for (int i = 0; i < 32; i += 8)
        Wt[(size_t)(n0 + y + i) * K + k0 + x] = t[x][y + i];
}

// ============ V transpose: qkv V slice -> vt[bh][d][j] =======================
__global__ __launch_bounds__(256) void vt_kernel(
    const float* __restrict__ qkv, float* __restrict__ vt)
{
    __shared__ float t[32][33];
    const int bh = blockIdx.z, b = bh >> 3, h = bh & 7;
    const int j0 = blockIdx.x * 32, d0 = blockIdx.y * 32;
    const int x = threadIdx.x, y = threadIdx.y;  // 32 x 8
#pragma unroll
    for (int i = 0; i < 32; i += 8)
        t[y + i][x] = qkv[((size_t)b * NSEQ + j0 + y + i) * 1536 + 1024 + h * 64 + d0 + x];
    __syncthreads();
#pragma unroll
    for (int i = 0; i < 32; i += 8)
        vt[((size_t)bh * 64 + d0 + y + i) * NSEQ + j0 + x] = t[x][y + i];
}

// ================ bf16x3 mma GEMM: C = A[M,K] @ Bt[N,K]^T ====================
#define LDS 40

__global__ __launch_bounds__(256, 2) void mma_gemm_kernel(
    const float* __restrict__ A, const float* __restrict__ Bt,
    float* __restrict__ C, const float* __restrict__ bias,
    const float* __restrict__ res, int M, int N, int K, int act)
{
    __shared__ __nv_bfloat16 sAh[128 * LDS];
    __shared__ __nv_bfloat16 sAl[128 * LDS];
    __shared__ __nv_bfloat16 sBh[128 * LDS];
    __shared__ __nv_bfloat16 sBl[128 * LDS];

    const int tid = threadIdx.x, wid = tid >> 5, lane = tid & 31;
    const int wm = wid >> 2, wn = wid & 3;
    const int bm = blockIdx.y * 128, bn = blockIdx.x * 128;

    const uint32_t aAh = smem_u32(sAh), aAl = smem_u32(sAl);
    const uint32_t aBh = smem_u32(sBh), aBl = smem_u32(sBl);

    const int l15 = lane & 15;
    const uint32_t aoff = (uint32_t)(((wm * 64 + l15) * LDS + ((lane >> 4) << 3)) * 2);
    const uint32_t boff = (uint32_t)(((wn * 32 + (l15 & 7)) * LDS + (((l15 >> 3) & 1) << 3)) * 2);

    float acc[4][4][4];
#pragma unroll
    for (int i = 0; i < 4; ++i)
#pragma unroll
        for (int j = 0; j < 4; ++j)
#pragma unroll
            for (int q = 0; q < 4; ++q) acc[i][j][q] = 0.0f;

    const int NKT = K >> 5;
    for (int kt = 0; kt < NKT; ++kt) {
        const int k0 = kt * 32;
#pragma unroll
        for (int i = 0; i < 4; ++i) {
            const int idx = tid + i * 256;
            const int row = idx >> 3, cg = (idx & 7) * 4;
            const uint32_t so = (uint32_t)((row * LDS + cg) * 2);
            uint2 hi, lo;
            split4(*(const float4*)(A + (size_t)(bm + row) * K + k0 + cg), hi, lo);
            *(uint2*)((char*)sAh + so) = hi;
            *(uint2*)((char*)sAl + so) = lo;
            split4(*(const float4*)(Bt + (size_t)(bn + row) * K + k0 + cg), hi, lo);
            *(uint2*)((char*)sBh + so) = hi;
            *(uint2*)((char*)sBl + so) = lo;
        }
        __syncthreads();

#pragma unroll
        for (int kk = 0; kk < 32; kk += 16) {
            uint32_t bh[4][2], bl[4][2], a[4][4];
#pragma unroll
            for (int nt = 0; nt < 4; ++nt) {
                const uint32_t bo = boff + (uint32_t)((nt * 8 * LDS + kk) * 2);
                ldm_x2(bh[nt], aBh + bo);
                ldm_x2(bl[nt], aBl + bo);
            }
#pragma unroll
            for (int mt = 0; mt < 4; ++mt)
                ldm_x4(a[mt], aAh + aoff + (uint32_t)((mt * 16 * LDS + kk) * 2));
#pragma unroll
            for (int mt = 0; mt < 4; ++mt)
#pragma unroll
                for (int nt = 0; nt < 4; ++nt) {
                    mma_bf16(acc[mt][nt], a[mt], bh[nt]);
                    mma_bf16(acc[mt][nt], a[mt], bl[nt]);
                }
#pragma unroll
            for (int mt = 0; mt < 4; ++mt)
                ldm_x4(a[mt], aAl + aoff + (uint32_t)((mt * 16 * LDS + kk) * 2));
#pragma unroll
            for (int mt = 0; mt < 4; ++mt)
#pragma unroll
                for (int nt = 0; nt < 4; ++nt)
                    mma_bf16(acc[mt][nt], a[mt], bh[nt]);
        }
        __syncthreads();
    }

    const int g = lane >> 2, t2 = (lane & 3) * 2;
#pragma unroll
    for (int mt = 0; mt < 4; ++mt) {
#pragma unroll
        for (int nt = 0; nt < 4; ++nt) {
            const int r0 = bm + wm * 64 + mt * 16 + g;
            const int r1 = r0 + 8;
            const int c  = bn + wn * 32 + nt * 8 + t2;
            float v0 = acc[mt][nt][0], v1 = acc[mt][nt][1];
            float v2 = acc[mt][nt][2], v3 = acc[mt][nt][3];
            if (bias) {
                const float b0 = bias[c], b1 = bias[c + 1];
                v0 += b0; v1 += b1; v2 += b0; v3 += b1;
            }
            if (act) {
                v0 = gelu_exact(v0); v1 = gelu_exact(v1);
                v2 = gelu_exact(v2); v3 = gelu_exact(v3);
            }
            if (res) {
                const float2 q0 = *(const float2*)(res + (size_t)r0 * N + c);
                const float2 q1 = *(const float2*)(res + (size_t)r1 * N + c);
                v0 += q0.x; v1 += q0.y; v2 += q1.x; v3 += q1.y;
            }
            *(float2*)(C + (size_t)r0 * N + c) = make_float2(v0, v1);
            *(float2*)(C + (size_t)r1 * N + c) = make_float2(v2, v3);
        }
    }
}

// ========== acbd via bf16x3 mma: z<64 -> AC = Qb K^T; z>=64 -> BD = Qb KR^T ==
__global__ __launch_bounds__(256, 2) void acbd_mma_kernel(
    const float* __restrict__ qkv, const float* __restrict__ kr,
    const float* __restrict__ bias_pf,
    float* __restrict__ AC, float* __restrict__ BD)
{
    __shared__ __nv_bfloat16 sAh[128 * LDS];
    __shared__ __nv_bfloat16 sAl[128 * LDS];
    __shared__ __nv_bfloat16 sBh[128 * LDS];
    __shared__ __nv_bfloat16 sBl[128 * LDS];

    const int tid = threadIdx.x, wid = tid >> 5, lane = tid & 31;
    const int wm = wid >> 2, wn = wid & 3;
    const int z = blockIdx.z, bh_idx = z & 63, isBD = z >> 6;
    const int b = bh_idx >> 3, h = bh_idx & 7;
    const int i0 = blockIdx.y * 128, j0 = blockIdx.x * 128;

    const float* Abase = qkv + ((size_t)b * NSEQ + i0) * 1536 + h * 64;
    const float* Bbase = isBD ? (kr + ((size_t)b * NSEQ + j0) * 512 + h * 64)
                              : (qkv + ((size_t)b * NSEQ + j0) * 1536 + 512 + h * 64);
    const int ldb = isBD ? 512 : 1536;
    float* Cbase = (isBD ? BD : AC) + (size_t)bh_idx * NSEQ * NSEQ;

    const uint32_t aAh = smem_u32(sAh), aAl = smem_u32(sAl);
    const uint32_t aBh = smem_u32(sBh), aBl = smem_u32(sBl);
    const int l15 = lane & 15;
    const uint32_t aoff = (uint32_t)(((wm * 64 + l15) * LDS + ((lane >> 4) << 3)) * 2);
    const uint32_t boff = (uint32_t)(((wn * 32 + (l15 & 7)) * LDS + (((l15 >> 3) & 1) << 3)) * 2);

    float acc[4][4][4];
#pragma unroll
    for (int i = 0; i < 4; ++i)
#pragma unroll
        for (int j = 0; j < 4; ++j)
#pragma unroll
            for (int q = 0; q < 4; ++q) acc[i][j][q] = 0.0f;

#pragma unroll
    for (int kt = 0; kt < 2; ++kt) {
        const int k0 = kt * 32;
#pragma unroll
        for (int i = 0; i < 4; ++i) {
            const int idx = tid + i * 256;
            const int row = idx >> 3, cg = (idx & 7) * 4;
            const uint32_t so = (uint32_t)((row * LDS + cg) * 2);
            float4 v = *(const float4*)(Abase + (size_t)row * 1536 + k0 + cg);
            float4 bp = *(const float4*)(bias_pf + h * 64 + k0 + cg);
            v.x += bp.x; v.y += bp.y; v.z += bp.z; v.w += bp.w;
            uint2 hi, lo;
            split4(v, hi, lo);
            *(uint2*)((char*)sAh + so) = hi;
            *(uint2*)((char*)sAl + so) = lo;
            split4(*(const float4*)(Bbase + (size_t)row * ldb + k0 + cg), hi, lo);
            *(uint2*)((char*)sBh + so) = hi;
            *(uint2*)((char*)sBl + so) = lo;
        }
        __syncthreads();

#pragma unroll
        for (int kk = 0; kk < 32; kk += 16) {
            uint32_t bh[4][2], bl[4][2], a[4][4];
#pragma unroll
            for (int nt = 0; nt < 4; ++nt) {
                const uint32_t bo = boff + (uint32_t)((nt * 8 * LDS + kk) * 2);
                ldm_x2(bh[nt], aBh + bo);
                ldm_x2(bl[nt], aBl + bo);
            }
#pragma unroll
            for (int mt = 0; mt < 4; ++mt)
                ldm_x4(a[mt], aAh + aoff + (uint32_t)((mt * 16 * LDS + kk) * 2));
#pragma unroll
            for (int mt = 0; mt < 4; ++mt)
#pragma unroll
                for (int nt = 0; nt < 4; ++nt) {
                    mma_bf16(acc[mt][nt], a[mt], bh[nt]);
                    mma_bf16(acc[mt][nt], a[mt], bl[nt]);
                }
#pragma unroll
            for (int mt = 0; mt < 4; ++mt)
                ldm_x4(a[mt], aAl + aoff + (uint32_t)((mt * 16 * LDS + kk) * 2));
#pragma unroll
            for (int mt = 0; mt < 4; ++mt)
#pragma unroll
                for (int nt = 0; nt < 4; ++nt)
                    mma_bf16(acc[mt][nt], a[mt], bh[nt]);
        }
        __syncthreads();
    }

    const int g = lane >> 2, t2 = (lane & 3) * 2;
#pragma unroll
    for (int mt = 0; mt < 4; ++mt) {
#pragma unroll
        for (int nt = 0; nt < 4; ++nt) {
            const int r0 = i0 + wm * 64 + mt * 16 + g;
            const int c  = j0 + wn * 32 + nt * 8 + t2;
            *(float2*)(Cbase + (size_t)r0 * NSEQ + c) =
                make_float2(acc[mt][nt][0], acc[mt][nt][1]);
            *(float2*)(Cbase + (size_t)(r0 + 8) * NSEQ + c) =
                make_float2(acc[mt][nt][2], acc[mt][nt][3]);
        }
    }
}

// ========== av via bf16x3 mma: out[b,i,h*64+d] = attn[bh] @ Vt[bh]^T ========
// CTA tile 128(m) x 64(n), K=1024. 8 warps 4x2, warp tile 32x32.
__global__ __launch_bounds__(256, 2) void av_mma_kernel(
    const float* __restrict__ attn, const float* __restrict__ vt,
    float* __restrict__ out)
{
    __shared__ __nv_bfloat16 sAh[128 * LDS];
    __shared__ __nv_bfloat16 sAl[128 * LDS];
    __shared__ __nv_bfloat16 sBh[64 * LDS];
    __shared__ __nv_bfloat16 sBl[64 * LDS];

    const int tid = threadIdx.x, wid = tid >> 5, lane = tid & 31;
    const int wm = wid >> 1, wn = wid & 1;     // 4 x 2 warp grid
    const int bh_idx = blockIdx.y, b = bh_idx >> 3, h = bh_idx & 7;
    const int i0 = blockIdx.x * 128;

    const float* Abase = attn + ((size_t)bh_idx * NSEQ + i0) * NSEQ;
    const float* Bbase = vt + (size_t)bh_idx * 64 * NSEQ;

    const uint32_t aAh = smem_u32(sAh), aAl = smem_u32(sAl);
    const uint32_t aBh = smem_u32(sBh), aBl = smem_u32(sBl);
    const int l15 = lane & 15;
    const uint32_t aoff = (uint32_t)(((wm * 32 + l15) * LDS + ((lane >> 4) << 3)) * 2);
    const uint32_t boff = (uint32_t)(((wn * 32 + (l15 & 7)) * LDS + (((l15 >> 3) & 1) << 3)) * 2);

    float acc[2][4][4];
#pragma unroll
    for (int i = 0; i < 2; ++i)
#pragma unroll
        for (int j = 0; j < 4; ++j)
#pragma unroll
            for (int q = 0; q < 4; ++q) acc[i][j][q] = 0.0f;

    for (int kt = 0; kt < 32; ++kt) {
        const int k0 = kt * 32;
        // A: 128 x 32
#pragma unroll
        for (int i = 0; i < 4; ++i) {
            const int idx = tid + i * 256;
            const int row = idx >> 3, cg = (idx & 7) * 4;
            const uint32_t so = (uint32_t)((row * LDS + cg) * 2);
            uint2 hi, lo;
            split4(*(const float4*)(Abase + (size_t)row * NSEQ + k0 + cg), hi, lo);
            *(uint2*)((char*)sAh + so) = hi;
            *(uint2*)((char*)sAl + so) = lo;
        }
        // B: 64 x 32
#pragma unroll
        for (int i = 0; i < 2; ++i) {
            const int idx = tid + i * 256;
            const int row = idx >> 3, cg = (idx & 7) * 4;
            const uint32_t so = (uint32_t)((row * LDS + cg) * 2);
            uint2 hi, lo;
            split4(*(const float4*)(Bbase + (size_t)row * NSEQ + k0 + cg), hi, lo);
            *(uint2*)((char*)sBh + so) = hi;
            *(uint2*)((char*)sBl + so) = lo;
        }
        __syncthreads();

#pragma unroll
        for (int kk = 0; kk < 32; kk += 16) {
            uint32_t bh[4][2], bl[4][2], a[2][4];
#pragma unroll
            for (int nt = 0; nt < 4; ++nt) {
                const uint32_t bo = boff + (uint32_t)((nt * 8 * LDS + kk) * 2);
                ldm_x2(bh[nt], aBh + bo);
                ldm_x2(bl[nt], aBl + bo);
            }
#pragma unroll
            for (int mt = 0; mt < 2; ++mt)
                ldm_x4(a[mt], aAh + aoff + (uint32_t)((mt * 16 * LDS + kk) * 2));
#pragma unroll
            for (int mt = 0; mt < 2; ++mt)
#pragma unroll
                for (int nt = 0; nt < 4; ++nt) {
                    mma_bf16(acc[mt][nt], a[mt], bh[nt]);
                    mma_bf16(acc[mt][nt], a[mt], bl[nt]);
                }
#pragma unroll
            for (int mt = 0; mt < 2; ++mt)
                ldm_x4(a[mt], aAl + aoff + (uint32_t)((mt * 16 * LDS + kk) * 2));
#pragma unroll
            for (int mt = 0; mt < 2; ++mt)
#pragma unroll
                for (int nt = 0; nt < 4; ++nt)
                    mma_bf16(acc[mt][nt], a[mt], bh[nt]);
        }
        __syncthreads();
    }

    const int g = lane >> 2, t2 = (lane & 3) * 2;
#pragma unroll
    for (int mt = 0; mt < 2; ++mt) {
#pragma unroll
        for (int nt = 0; nt < 4; ++nt) {
            const int r0 = i0 + wm * 32 + mt * 16 + g;
            const int c  = h * 64 + wn * 32 + nt * 8 + t2;
            *(float2*)(out + ((size_t)b * NSEQ + r0) * NHD + c) =
                make_float2(acc[mt][nt][0], acc[mt][nt][1]);
            *(float2*)(out + ((size_t)b * NSEQ + r0 + 8) * NHD + c) =
                make_float2(acc[mt][nt][2], acc[mt][nt][3]);
        }
    }
}

// ---------------- LayerNorm ------------------------------------------------
__global__ __launch_bounds__(128) void ln_kernel(
    const float* __restrict__ x, const float* __restrict__ g,
    const float* __restrict__ b, float* __restrict__ y)
{
    const int row = blockIdx.x;
    const int tid = threadIdx.x;
    const float* xr = x + (size_t)row * NDIM;
    float*       yr = y + (size_t)row * NDIM;

    float4 v = ((const float4*)xr)[tid];
    float s  = v.x + v.y + v.z + v.w;
    float sq = v.x*v.x + v.y*v.y + v.z*v.z + v.w*v.w;
#pragma unroll
    for (int o = 16; o > 0; o >>= 1) {
        s  += __shfl_xor_sync(0xffffffffu, s,  o);
        sq += __shfl_xor_sync(0xffffffffu, sq, o);
    }
    __shared__ float red[8];
    const int w = tid >> 5;
    if ((tid & 31) == 0) { red[w] = s; red[4 + w] = sq; }
    __syncthreads();
    const float st  = red[0] + red[1] + red[2] + red[3];
    const float sqt = red[4] + red[5] + red[6] + red[7];
    const float mu  = st * (1.0f / NDIM);
    const float var = sqt * (1.0f / NDIM) - mu * mu;
    const float inv = rsqrtf(var + 1e-5f);

    float4 gg = ((const float4*)g)[tid];
    float4 bb = ((const float4*)b)[tid];
    float4 o;
    o.x = (v.x - mu) * inv * gg.x + bb.x;
    o.y = (v.y - mu) * inv * gg.y + bb.y;
    o.z = (v.z - mu) * inv * gg.z + bb.z;
    o.w = (v.w - mu) * inv * gg.w + bb.w;
    ((float4*)yr)[tid] = o;
}

// ---------------- rel_shift + scale + softmax over heads -------------------
__global__ __launch_bounds__(256) void softmax_shift_kernel(
    const float* AC, const float* __restrict__ BDp, float* attn)
{
    const int j = blockIdx.x * blockDim.x + threadIdx.x;
    const int i = blockIdx.y;
    const int b = blockIdx.z;
    const int g  = (i + 1) * NSEQ + j;
    const int si = g / (NSEQ + 1);
    const int sj = g % (NSEQ + 1) - 1;

    float v[NHEADS];
    float mx = -1e30f;
#pragma unroll
    for (int h = 0; h < NHEADS; ++h) {
        const size_t idx = (((size_t)(b * NHEADS + h)) * NSEQ + i) * NSEQ + j;
        float acv = AC[idx];
        float bdv = 0.0f;
        if (sj >= 0)
            bdv = BDp[(((size_t)(b * NHEADS + h)) * NSEQ + si) * NSEQ + sj];
        const float d = (acv + bdv) * 0.125f;
        v[h] = d;
        mx = fmaxf(mx, d);
    }
    float s = 0.0f;
#pragma unroll
    for (int h = 0; h < NHEADS; ++h) { v[h] = __expf(v[h] - mx); s += v[h]; }
    const float inv = 1.0f / s;
#pragma unroll
    for (int h = 0; h < NHEADS; ++h) {
        const size_t idx = (((size_t)(b * NHEADS + h)) * NSEQ + i) * NSEQ + j;
        attn[idx] = v[h] * inv;
    }
}

// ---------------- host orchestration ---------------------------------------
extern "C" void kernel_launch(void* const* d_in, const int* in_sizes, int n_in,
                              void* d_out, int out_size)
{
    (void)in_sizes; (void)n_in;
    const float* x_in    = (const float*)d_in[0];
    const float* r_t     = (const float*)d_in[1];
    const float* bias_pf = (const float*)d_in[3];
    const float* ln1_g   = (const float*)d_in[4];
    const float* ln1_b   = (const float*)d_in[5];
    const float* Wqkv    = (const float*)d_in[6];
    const float* Wkr_t   = (const float*)d_in[7];
    const float* Wout    = (const float*)d_in[9];
    const float* bout    = (const float*)d_in[10];
    const float* ln2_g   = (const float*)d_in[11];
    const float* ln2_b   = (const float*)d_in[12];
    const float* W1      = (const float*)d_in[13];
    const float* b1      = (const float*)d_in[14];
    const float* W2      = (const float*)d_in[15];
    const float* b2      = (const float*)d_in[16];
    float* outp = (float*)d_out;

    float *gx, *gxn, *gqkv, *gkr, *gac, *gbd, *gav, *gff, *gwt, *gvt;
    cudaGetSymbolAddress((void**)&gx,   g_x);
    cudaGetSymbolAddress((void**)&gxn,  g_xn);
    cudaGetSymbolAddress((void**)&gqkv, g_qkv);
    cudaGetSymbolAddress((void**)&gkr,  g_kr);
    cudaGetSymbolAddress((void**)&gac,  g_ac);
    cudaGetSymbolAddress((void**)&gbd,  g_bd);
    cudaGetSymbolAddress((void**)&gav,  g_av);
    cudaGetSymbolAddress((void**)&gff,  g_ff);
    cudaGetSymbolAddress((void**)&gwt,  g_wt);
    cudaGetSymbolAddress((void**)&gvt,  g_vt);

    float* attn_out = outp + ((size_t)out_size - ATT_ELEMS);

    cudaMemcpyAsync(gx, x_in, X_ELEMS * sizeof(float), cudaMemcpyDeviceToDevice, 0);

    const dim3 tb(32, 8);
    for (int l = 0; l < 4; ++l) {
        // transpose this layer's weights into [N][K]
        transpose_kernel<<<dim3(1536/32, 512/32), tb>>>(Wqkv  + (size_t)l*512*1536, gwt + WQKVT, 512, 1536);
        transpose_kernel<<<dim3(512/32,  512/32), tb>>>(Wkr_t + (size_t)l*512*512,  gwt + WKRT,  512, 512);
        transpose_kernel<<<dim3(512/32,  512/32), tb>>>(Wout  + (size_t)l*512*512,  gwt + WOUTT, 512, 512);
        transpose_kernel<<<dim3(2048/32, 512/32), tb>>>(W1    + (size_t)l*512*2048, gwt + W1T,   512, 2048);
        transpose_kernel<<<dim3(512/32, 2048/32), tb>>>(W2    + (size_t)l*2048*512, gwt + W2T,  2048, 512);

        // PreNorm + QKV + relative key projection (bf16x3 mma)
        ln_kernel<<<MROWS, 128>>>(gx, ln1_g + l * NDIM, ln1_b + l * NDIM, gxn);
        mma_gemm_kernel<<<dim3(12, 64), 256>>>(
            gxn, gwt + WQKVT, gqkv, nullptr, nullptr, MROWS, 1536, 512, 0);
        mma_gemm_kernel<<<dim3(4, 64), 256>>>(
            r_t, gwt + WKRT, gkr, nullptr, nullptr, MROWS, 512, 512, 0);

        // batched AC / BD via tensor cores
        acbd_mma_kernel<<<dim3(8, 8, 128), 256>>>(gqkv, gkr, bias_pf, gac, gbd);

        // V transpose for av mma
        vt_kernel<<<dim3(32, 2, 64), tb>>>(gqkv, gvt);

        // rel_shift + scale + softmax over heads
        float* attn = (l == 3) ? attn_out : gac;
        softmax_shift_kernel<<<dim3(NSEQ / 256, NSEQ, NBATCH), 256>>>(gac, gbd, attn);

        // out = attn @ V via tensor cores
        av_mma_kernel<<<dim3(8, 64), 256>>>(attn, gvt, gav);

        // x = out @ Wout + bout + x
        mma_gemm_kernel<<<dim3(4, 64), 256>>>(
            gav, gwt + WOUTT, gx, bout + l * NDIM, gx, MROWS, 512, 512, 0);

        // FFN
        ln_kernel<<<MROWS, 128>>>(gx, ln2_g + l * NDIM, ln2_b + l * NDIM, gxn);
        mma_gemm_kernel<<<dim3(16, 64), 256>>>(
            gxn, gwt + W1T, gff, b1 + l * NFF, nullptr, MROWS, 2048, 512, 1);
        float* xdst = (l == 3) ? outp : gx;
        mma_gemm_kernel<<<dim3(4, 64), 256>>>(
            gff, gwt + W2T, xdst, b2 + l * NDIM, gx, MROWS, 512, 2048, 0);
    }
}